// round 11
// baseline (speedup 1.0000x reference)
#include <cuda_runtime.h>

#define Bn 16
#define Cn 64
#define Hn 256
#define Wn 256
#define PHn 128
#define PWn 128
#define CH_STRIDE (Hn * Wn)      // 65536 floats between channels (feature)
#define PCH_STRIDE (PHn * PWn)   // 16384 floats between channels (pooled)

typedef unsigned long long u64;

// scratch (static __device__ — allocation-free per harness rules)
__device__ float g_pooled[Bn * Cn * PHn * PWn];  // 64 MiB

// ---- f32x2 helpers -------------------------------------------------------
__device__ __forceinline__ void fma2(u64& d, u64 a, u64 b) {
    asm("fma.rn.f32x2 %0, %1, %2, %0;" : "+l"(d) : "l"(a), "l"(b));
}
__device__ __forceinline__ float2 unpack2(u64 v) {
    float2 r;
    asm("mov.b64 {%0, %1}, %2;" : "=f"(r.x), "=f"(r.y) : "l"(v));
    return r;
}
__device__ __forceinline__ u64 as_u64(float2 v) {
    u64 r;
    asm("mov.b64 %0, {%1, %2};" : "=l"(r) : "f"(v.x), "f"(v.y));
    return r;
}

// ---- cp.async helpers ----------------------------------------------------
__device__ __forceinline__ void cp_async16(unsigned int smem_dst, const float* src) {
    asm volatile("cp.async.cg.shared.global [%0], [%1], 16;" :: "r"(smem_dst), "l"(src));
}
__device__ __forceinline__ void cp_commit() { asm volatile("cp.async.commit_group;"); }
__device__ __forceinline__ void cp_wait0()  { asm volatile("cp.async.wait_group 0;"); }

// ---------------------------------------------------------------------------
// Pass 1: avg_pool2d k=3 s=2 pad=1 (count_include_pad: always /9).
// ~84% DRAM — near unique-traffic roofline; unchanged.
// ---------------------------------------------------------------------------
__global__ __launch_bounds__(256) void pool_kernel(const float* __restrict__ feat) {
    int idx = blockIdx.x * 256 + threadIdx.x;
    int pwq = idx & 31;
    int t   = idx >> 5;
    int ph  = t & 127;
    int bc  = t >> 7;
    const float* src = feat + (size_t)bc * (Hn * Wn);
    int c0 = pwq << 3;

    float s0 = 0.f, s1 = 0.f, s2 = 0.f, s3 = 0.f;
    int rbase = 2 * ph - 1;
#pragma unroll
    for (int rr = 0; rr < 3; rr++) {
        int r = rbase + rr;
        if (r < 0) continue;
        const float* row = src + r * Wn;
        float left = (c0 > 0) ? __ldcs(row + c0 - 1) : 0.f;
        float4 a  = __ldcs(reinterpret_cast<const float4*>(row + c0));
        float4 b4 = __ldcs(reinterpret_cast<const float4*>(row + c0 + 4));
        s0 += left + a.x  + a.y;
        s1 += a.y  + a.z  + a.w;
        s2 += a.w  + b4.x + b4.y;
        s3 += b4.y + b4.z + b4.w;
    }
    const float inv9 = 1.0f / 9.0f;
    float4 o = make_float4(s0 * inv9, s1 * inv9, s2 * inv9, s3 * inv9);
    *reinterpret_cast<float4*>(g_pooled + (size_t)bc * PCH_STRIDE + ph * PWn + (pwq << 2)) = o;
}

// ---------------------------------------------------------------------------
// Pass 2: diff + fused P2. Block = 16x16 quads = 32x32 output tile.
// Feature tile: cp.async double-buffered (4 channels/stage).
// Pooled halo: register-prefetched via LDG (L2-resident) one chunk ahead,
// written to smem as DUPLICATED float2 {v,v} cells -> the f32x2 broadcast
// operand is one aligned LDS.64, no MOV pair duplication.
// jnp.roll wrap handled by &127 in the precomputed gather offsets.
// ---------------------------------------------------------------------------
#define CHUNK  4
#define HALO   324                 // 18*18 halo cells
#define NCELLS (CHUNK * HALO)      // 1296 per chunk
#define FROW   32                  // feature smem row (floats, unpadded)
#define FCH    (32 * FROW)         // 1024 floats per staged channel
#define NITER  (Cn / CHUNK)        // 16

__global__ __launch_bounds__(256, 4) void diff_kernel(const float* __restrict__ feat,
                                                      float* __restrict__ out) {
    __shared__ __align__(16) float  sfeat[2][CHUNK * FCH];  // 32,768 B
    __shared__ __align__(16) float2 sdup[NCELLS];           // 10,368 B (single buffer)

    int b   = blockIdx.z;
    int ph0 = blockIdx.y << 4;
    int pw0 = blockIdx.x << 4;
    int tid = threadIdx.x;
    int qx  = tid & 15, qy = tid >> 4;

    const float* fimg = feat + (size_t)b * Cn * CH_STRIDE;
    const float* pimg = g_pooled + (size_t)b * Cn * PCH_STRIDE;
    unsigned int sfeat_a = (unsigned int)__cvta_generic_to_shared(&sfeat[0][0]);

    // ---- feature staging constants: 1 cp16 per channel per thread ----
    int frow = tid >> 3;
    int fcol = (tid & 7) << 2;
    const float* fsrc0 = fimg + (size_t)((ph0 << 1) + frow) * Wn + (pw0 << 1) + fcol;
    unsigned int fdst0 = sfeat_a + (unsigned)(frow * FROW + fcol) * 4;

    // cc is a CHANNEL BASE (not an iteration index)
    auto stage_feat = [&](int buf, int cc) {
        unsigned int fd = fdst0 + buf * (CHUNK * FCH * 4);
        const float* fs = fsrc0 + (size_t)cc * CH_STRIDE;
#pragma unroll
        for (int m = 0; m < CHUNK; m++) {
            cp_async16(fd + m * (FCH * 4), fs);
            fs += CH_STRIDE;
        }
        cp_commit();
    };

    // ---- halo gather offsets (cells tid + 256u; wrap via &127) ----
    int poff[6];
#pragma unroll
    for (int u = 0; u < 6; u++) {
        int k = tid + 256 * u;
        int kk = (k < NCELLS) ? k : 0;
        int c = kk / HALO;
        int r = kk - c * HALO;
        int i = r / 18;
        int j = r - i * 18;
        int gr = (ph0 - 1 + i) & 127;
        int gc = (pw0 - 1 + j) & 127;
        poff[u] = c * PCH_STRIDE + (gr << 7) + gc;
    }
    bool has5 = (tid + 256 * 5 < NCELLS);   // u=0..4 always valid

    // ---- prologue: prefetch halo chunk 0, stage feature chunk 0 ----
    float h[6];
#pragma unroll
    for (int u = 0; u < 5; u++) h[u] = pimg[poff[u]];
    h[5] = has5 ? pimg[poff[5]] : 0.f;
    const float* pnext = pimg + CHUNK * PCH_STRIDE;
    stage_feat(0, 0);

    // ---- accumulators ----
    u64 z = 0;
    u64 cr01[8], cr23[8];
#pragma unroll
    for (int s = 0; s < 8; s++) { cr01[s] = z; cr23[s] = z; }
    u64 F2_01 = z, F2_23 = z;
    float p2acc0 = 0.f, p2acc1 = 0.f;
    bool has1 = (tid + 256 < HALO);
    int sbase = (qy + 1) * 18 + (qx + 1);
    int qoff  = (qy << 1) * FROW + (qx << 1);

    for (int it = 0; it < NITER; it++) {
        int cur = it & 1;
        cp_wait0();
        __syncthreads();          // feat(it) staged; prev chunk's sdup reads done

        // ---- publish duplicated halo cells from prefetch registers ----
#pragma unroll
        for (int u = 0; u < 5; u++) sdup[tid + 256 * u] = make_float2(h[u], h[u]);
        if (has5) sdup[tid + 256 * 5] = make_float2(h[5], h[5]);

        // ---- prefetch next chunk (feature cp.async + halo LDG) ----
        if (it + 1 < NITER) {
            stage_feat(1 - cur, (it + 1) * CHUNK);   // FIX: channel base, not it+1
#pragma unroll
            for (int u = 0; u < 5; u++) h[u] = pnext[poff[u]];
            if (has5) h[5] = pnext[poff[5]];
            pnext += CHUNK * PCH_STRIDE;
        }
        __syncthreads();          // sdup visible

        // ---- P2 fold (reads .x of dup cells) ----
        {
            const float* dupf = reinterpret_cast<const float*>(sdup);
#pragma unroll
            for (int c = 0; c < CHUNK; c++) {
                float v = dupf[2 * (c * HALO + tid)];
                p2acc0 += v * v;
            }
            if (has1) {
#pragma unroll
                for (int c = 0; c < CHUNK; c++) {
                    float v = dupf[2 * (c * HALO + tid + 256)];
                    p2acc1 += v * v;
                }
            }
        }

        // ---- quad accumulation: ps pairs are single LDS.64 each ----
#pragma unroll
        for (int c = 0; c < CHUNK; c++) {
            const float* fp = &sfeat[cur][c * FCH + qoff];
            u64 f01 = as_u64(*reinterpret_cast<const float2*>(fp));
            u64 f23 = as_u64(*reinterpret_cast<const float2*>(fp + FROW));

            const float2* dp = sdup + c * HALO + sbase;
            u64 pp0 = as_u64(dp[-19]);
            u64 pp1 = as_u64(dp[-18]);
            u64 pp2 = as_u64(dp[-17]);
            u64 pp3 = as_u64(dp[-1]);
            u64 pp4 = as_u64(dp[ 1]);
            u64 pp5 = as_u64(dp[17]);
            u64 pp6 = as_u64(dp[18]);
            u64 pp7 = as_u64(dp[19]);

            fma2(F2_01, f01, f01);
            fma2(F2_23, f23, f23);
            fma2(cr01[0], f01, pp0); fma2(cr23[0], f23, pp0);
            fma2(cr01[1], f01, pp1); fma2(cr23[1], f23, pp1);
            fma2(cr01[2], f01, pp2); fma2(cr23[2], f23, pp2);
            fma2(cr01[3], f01, pp3); fma2(cr23[3], f23, pp3);
            fma2(cr01[4], f01, pp4); fma2(cr23[4], f23, pp4);
            fma2(cr01[5], f01, pp5); fma2(cr23[5], f23, pp5);
            fma2(cr01[6], f01, pp6); fma2(cr23[6], f23, pp6);
            fma2(cr01[7], f01, pp7); fma2(cr23[7], f23, pp7);
        }
    }

    // ---- publish P2 tile into reused smem (sdup storage) ----
    __syncthreads();                            // all sdup reads complete
    float* sP2 = reinterpret_cast<float*>(sdup);
    sP2[tid] = p2acc0;
    if (has1) sP2[tid + 256] = p2acc1;
    __syncthreads();

    float P2n[8];
    P2n[0] = sP2[sbase - 19]; P2n[1] = sP2[sbase - 18]; P2n[2] = sP2[sbase - 17];
    P2n[3] = sP2[sbase - 1];                             P2n[4] = sP2[sbase + 1];
    P2n[5] = sP2[sbase + 17]; P2n[6] = sP2[sbase + 18]; P2n[7] = sP2[sbase + 19];

    float2 F2p01 = unpack2(F2_01);
    float2 F2p23 = unpack2(F2_23);
    float F2arr[4] = {F2p01.x, F2p01.y, F2p23.x, F2p23.y};

    float res[4] = {-3.4e38f, -3.4e38f, -3.4e38f, -3.4e38f};
#pragma unroll
    for (int s = 0; s < 8; s++) {
        float2 c01 = unpack2(cr01[s]);
        float2 c23 = unpack2(cr23[s]);
        res[0] = fmaxf(res[0], F2arr[0] - 2.f * c01.x + P2n[s]);
        res[1] = fmaxf(res[1], F2arr[1] - 2.f * c01.y + P2n[s]);
        res[2] = fmaxf(res[2], F2arr[2] - 2.f * c23.x + P2n[s]);
        res[3] = fmaxf(res[3], F2arr[3] - 2.f * c23.y + P2n[s]);
    }

    int ph = ph0 + qy, pw = pw0 + qx;
    float* orow = out + (size_t)b * (Hn * Wn) + (ph << 1) * Wn + (pw << 1);
    *reinterpret_cast<float2*>(orow)      = make_float2(res[0], res[1]);
    *reinterpret_cast<float2*>(orow + Wn) = make_float2(res[2], res[3]);
}

// ---------------------------------------------------------------------------
extern "C" void kernel_launch(void* const* d_in, const int* in_sizes, int n_in,
                              void* d_out, int out_size) {
    const float* feat = (const float*)d_in[0];
    float* out = (float*)d_out;
    // dist is fixed at 1 by the problem's setup_inputs (d = 2)

    pool_kernel<<<16384, 256>>>(feat);
    dim3 g(8, 8, Bn);
    diff_kernel<<<g, 256>>>(feat, out);
}

// round 13
// speedup vs baseline: 1.0095x; 1.0095x over previous
#include <cuda_runtime.h>

#define Bn 16
#define Cn 64
#define Hn 256
#define Wn 256
#define PHn 128
#define PWn 128
#define CH_STRIDE (Hn * Wn)      // 65536 floats between channels (feature)
#define PCH_STRIDE (PHn * PWn)   // 16384 floats between channels (pooled)

typedef unsigned long long u64;

// scratch (static __device__ — allocation-free per harness rules)
__device__ float g_pooled[Bn * Cn * PHn * PWn];  // 64 MiB

// ---- f32x2 helpers -------------------------------------------------------
__device__ __forceinline__ void fma2(u64& d, u64 a, u64 b) {
    asm("fma.rn.f32x2 %0, %1, %2, %0;" : "+l"(d) : "l"(a), "l"(b));
}
__device__ __forceinline__ u64 bcast2(float v) {
    u64 r;
    asm("mov.b64 %0, {%1, %2};" : "=l"(r) : "f"(v), "f"(v));
    return r;
}
__device__ __forceinline__ float2 unpack2(u64 v) {
    float2 r;
    asm("mov.b64 {%0, %1}, %2;" : "=f"(r.x), "=f"(r.y) : "l"(v));
    return r;
}
__device__ __forceinline__ u64 as_u64(float2 v) {
    u64 r;
    asm("mov.b64 %0, {%1, %2};" : "=l"(r) : "f"(v.x), "f"(v.y));
    return r;
}

// ---- cp.async helpers ----------------------------------------------------
__device__ __forceinline__ void cp_async4(unsigned int smem_dst, const float* src) {
    asm volatile("cp.async.ca.shared.global [%0], [%1], 4;" :: "r"(smem_dst), "l"(src));
}
__device__ __forceinline__ void cp_async16(unsigned int smem_dst, const float* src) {
    asm volatile("cp.async.cg.shared.global [%0], [%1], 16;" :: "r"(smem_dst), "l"(src));
}
__device__ __forceinline__ void cp_commit() { asm volatile("cp.async.commit_group;"); }
__device__ __forceinline__ void cp_wait0()  { asm volatile("cp.async.wait_group 0;"); }

// ---------------------------------------------------------------------------
// Pass 1: avg_pool2d k=3 s=2 pad=1 (count_include_pad: always /9).
// ~84% DRAM — near unique-traffic roofline; unchanged.
// ---------------------------------------------------------------------------
__global__ __launch_bounds__(256) void pool_kernel(const float* __restrict__ feat) {
    int idx = blockIdx.x * 256 + threadIdx.x;
    int pwq = idx & 31;
    int t   = idx >> 5;
    int ph  = t & 127;
    int bc  = t >> 7;
    const float* src = feat + (size_t)bc * (Hn * Wn);
    int c0 = pwq << 3;

    float s0 = 0.f, s1 = 0.f, s2 = 0.f, s3 = 0.f;
    int rbase = 2 * ph - 1;
#pragma unroll
    for (int rr = 0; rr < 3; rr++) {
        int r = rbase + rr;
        if (r < 0) continue;
        const float* row = src + r * Wn;
        float left = (c0 > 0) ? __ldcs(row + c0 - 1) : 0.f;
        float4 a  = __ldcs(reinterpret_cast<const float4*>(row + c0));
        float4 b4 = __ldcs(reinterpret_cast<const float4*>(row + c0 + 4));
        s0 += left + a.x  + a.y;
        s1 += a.y  + a.z  + a.w;
        s2 += a.w  + b4.x + b4.y;
        s3 += b4.y + b4.z + b4.w;
    }
    const float inv9 = 1.0f / 9.0f;
    float4 o = make_float4(s0 * inv9, s1 * inv9, s2 * inv9, s3 * inv9);
    *reinterpret_cast<float4*>(g_pooled + (size_t)bc * PCH_STRIDE + ph * PWn + (pwq << 2)) = o;
}

// ---------------------------------------------------------------------------
// Pass 2: diff + fused P2, SHIFT-SPLIT version (race-free pipeline).
// Block = 256 threads = 2 shift-groups x 128 threads; each group covers the
// SAME 16x8 quad tile (32x16 out pixels). Group 0 accumulates shifts
// {TL,T,TR,L}, group 1 {R,BL,B,BR}; 4 shift accumulators per thread.
// Pipeline: cp_wait0 -> __syncthreads -> stage(next) -> compute(cur).
// (stage AFTER the barrier: no thread can still be reading the target buffer.)
// ---------------------------------------------------------------------------
#define CHUNK  4
#define NITER  (Cn / CHUNK)        // 16
#define HROWS  10                  // halo rows (8 + 2)
#define HCOLS  18                  // halo cols (16 + 2)
#define HALO2  (HROWS * HCOLS)     // 180
#define FROW2  32                  // feature tile width (floats)
#define FTILE  (16 * FROW2)        // 512 floats per channel (16 rows x 32)
#define FBUFB  (CHUNK * FTILE * 4) // 8192 B per feature buffer
#define HBUFB  (CHUNK * HALO2 * 4) // 2880 B per halo buffer

__global__ __launch_bounds__(256, 5) void diff_kernel(const float* __restrict__ feat,
                                                      float* __restrict__ out) {
    __shared__ __align__(16) float sfeat[2][CHUNK * FTILE];  // 16,384 B
    __shared__ __align__(16) float shalo[2][CHUNK * HALO2];  //  5,760 B
    __shared__ float  sP2[HALO2];                            //    720 B
    __shared__ float4 sxch[128];                             //  2,048 B

    int b   = blockIdx.z;
    int ph0 = blockIdx.y << 3;       // 8 pooled rows per block
    int pw0 = blockIdx.x << 4;       // 16 pooled cols per block
    int tid = threadIdx.x;
    int sg  = tid >> 7;              // shift group 0/1
    int t   = tid & 127;
    int qx  = t & 15, qy = t >> 4;   // quad coords (16 x 8)

    const float* fimg = feat + (size_t)b * Cn * CH_STRIDE;
    const float* pimg = g_pooled + (size_t)b * Cn * PCH_STRIDE;
    unsigned int sfeat_a = (unsigned int)__cvta_generic_to_shared(&sfeat[0][0]);
    unsigned int shalo_a = (unsigned int)__cvta_generic_to_shared(&shalo[0][0]);

    // ---- feature staging: 512 cp16 per chunk -> 2 per thread ----
    int fsrc[2], fdst[2];
#pragma unroll
    for (int u = 0; u < 2; u++) {
        int k = tid + 256 * u;       // 0..511
        int c = k >> 7;              // channel-in-chunk 0..3
        int r = (k & 127) >> 3;      // tile row 0..15
        int g = k & 7;               // 4-col group 0..7
        fsrc[u] = c * CH_STRIDE + ((ph0 << 1) + r) * Wn + (pw0 << 1) + (g << 2);
        fdst[u] = ((c * 16 + r) * FROW2 + (g << 2)) * 4;
    }
    // ---- halo staging: 720 cp4 per chunk -> up to 3 per thread ----
    int hsrc[3], hdst[3];
    bool hok[3];
#pragma unroll
    for (int u = 0; u < 3; u++) {
        int k = tid + 256 * u;       // 0..767
        hok[u] = (k < CHUNK * HALO2);
        int kk = hok[u] ? k : 0;
        int c = kk / HALO2;
        int r = kk - c * HALO2;
        int i = r / HCOLS;
        int j = r - i * HCOLS;
        int gr = (ph0 - 1 + i) & 127;
        int gc = (pw0 - 1 + j) & 127;
        hsrc[u] = c * PCH_STRIDE + (gr << 7) + gc;
        hdst[u] = kk * 4;
    }

    auto stage = [&](int buf, int cc) {
        const float* fb = fimg + (size_t)cc * CH_STRIDE;
#pragma unroll
        for (int u = 0; u < 2; u++)
            cp_async16(sfeat_a + buf * FBUFB + fdst[u], fb + fsrc[u]);
        const float* pb = pimg + (size_t)cc * PCH_STRIDE;
#pragma unroll
        for (int u = 0; u < 3; u++)
            if (hok[u]) cp_async4(shalo_a + buf * HBUFB + hdst[u], pb + hsrc[u]);
        cp_commit();
    };

    // ---- per-group shift offsets within the dense halo tile ----
    int hs0, hs1, hs2, hs3;
    if (sg == 0) { hs0 = -HCOLS - 1; hs1 = -HCOLS; hs2 = -HCOLS + 1; hs3 = -1; }
    else         { hs0 = 1;          hs1 = HCOLS - 1; hs2 = HCOLS;   hs3 = HCOLS + 1; }
    int sbase = (qy + 1) * HCOLS + (qx + 1);
    int qoff  = (qy << 1) * FROW2 + (qx << 1);

    // ---- accumulators ----
    u64 z = 0;
    u64 cr01[4], cr23[4];
#pragma unroll
    for (int s = 0; s < 4; s++) { cr01[s] = z; cr23[s] = z; }
    u64 F2_01 = z, F2_23 = z;
    float p2acc = 0.f;
    bool ownp2 = (tid < HALO2);

    stage(0, 0);

    for (int it = 0; it < NITER; it++) {
        int cur = it & 1;
        cp_wait0();
        __syncthreads();                 // chunk it visible to ALL; all reads of
                                         // buffer 1-cur (iteration it-1) done
        if (it + 1 < NITER) stage(1 - cur, (it + 1) * CHUNK);

        const float* hbuf = &shalo[cur][0];
        const float* fbuf = &sfeat[cur][0];

        // ---- P2 fold (register-carried, owner thread per cell) ----
        if (ownp2) {
#pragma unroll
            for (int c = 0; c < CHUNK; c++) {
                float v = hbuf[c * HALO2 + tid];
                p2acc += v * v;
            }
        }

        // ---- quad accumulation: 4 shifts for this group ----
#pragma unroll
        for (int c = 0; c < CHUNK; c++) {
            const float* fp = fbuf + c * FTILE + qoff;
            u64 f01 = as_u64(*reinterpret_cast<const float2*>(fp));
            u64 f23 = as_u64(*reinterpret_cast<const float2*>(fp + FROW2));

            const float* hc = hbuf + c * HALO2 + sbase;
            u64 p0 = bcast2(hc[hs0]);
            u64 p1 = bcast2(hc[hs1]);
            u64 p2 = bcast2(hc[hs2]);
            u64 p3 = bcast2(hc[hs3]);

            fma2(F2_01, f01, f01);
            fma2(F2_23, f23, f23);
            fma2(cr01[0], f01, p0); fma2(cr23[0], f23, p0);
            fma2(cr01[1], f01, p1); fma2(cr23[1], f23, p1);
            fma2(cr01[2], f01, p2); fma2(cr23[2], f23, p2);
            fma2(cr01[3], f01, p3); fma2(cr23[3], f23, p3);
        }
    }

    // ---- publish P2 tile ----
    __syncthreads();                     // all halo reads complete
    if (ownp2) sP2[tid] = p2acc;
    __syncthreads();

    float P2n[4];
    P2n[0] = sP2[sbase + hs0];
    P2n[1] = sP2[sbase + hs1];
    P2n[2] = sP2[sbase + hs2];
    P2n[3] = sP2[sbase + hs3];

    float2 F2p01 = unpack2(F2_01);
    float2 F2p23 = unpack2(F2_23);
    float F2arr[4] = {F2p01.x, F2p01.y, F2p23.x, F2p23.y};

    float res[4] = {-3.4e38f, -3.4e38f, -3.4e38f, -3.4e38f};
#pragma unroll
    for (int s = 0; s < 4; s++) {
        float2 c01 = unpack2(cr01[s]);
        float2 c23 = unpack2(cr23[s]);
        res[0] = fmaxf(res[0], F2arr[0] - 2.f * c01.x + P2n[s]);
        res[1] = fmaxf(res[1], F2arr[1] - 2.f * c01.y + P2n[s]);
        res[2] = fmaxf(res[2], F2arr[2] - 2.f * c23.x + P2n[s]);
        res[3] = fmaxf(res[3], F2arr[3] - 2.f * c23.y + P2n[s]);
    }

    // ---- merge the two shift-groups' partial maxima ----
    if (sg == 1) sxch[t] = make_float4(res[0], res[1], res[2], res[3]);
    __syncthreads();
    if (sg == 0) {
        float4 r2 = sxch[t];
        res[0] = fmaxf(res[0], r2.x);
        res[1] = fmaxf(res[1], r2.y);
        res[2] = fmaxf(res[2], r2.z);
        res[3] = fmaxf(res[3], r2.w);

        int ph = ph0 + qy, pw = pw0 + qx;
        float* orow = out + (size_t)b * (Hn * Wn) + (ph << 1) * Wn + (pw << 1);
        *reinterpret_cast<float2*>(orow)      = make_float2(res[0], res[1]);
        *reinterpret_cast<float2*>(orow + Wn) = make_float2(res[2], res[3]);
    }
}

// ---------------------------------------------------------------------------
extern "C" void kernel_launch(void* const* d_in, const int* in_sizes, int n_in,
                              void* d_out, int out_size) {
    const float* feat = (const float*)d_in[0];
    float* out = (float*)d_out;
    // dist is fixed at 1 by the problem's setup_inputs (d = 2)

    pool_kernel<<<16384, 256>>>(feat);
    dim3 g(8, 16, Bn);
    diff_kernel<<<g, 256>>>(feat, out);
}